// round 6
// baseline (speedup 1.0000x reference)
#include <cuda_runtime.h>
#include <math.h>

// ---------------- problem constants ----------------
#define S_TOT   20197
#define BATCH   2
#define T_TOT   40394          // BATCH * S_TOT
#define DMODEL  256
#define NHEAD   8
#define HDIM    32
#define NLEV    4
#define NPNT    4
#define DFF     1024
#define NLAYERS 6

// level geometry
__device__ __forceinline__ void level_consts(int l, int& H, int& W, int& start) {
    const int Hs[4] = {100, 50, 25, 13};
    const int Ws[4] = {152, 76, 38, 19};
    const int St[4] = {0, 15200, 19000, 19950};
    H = Hs[l]; W = Ws[l]; start = St[l];
}

// ---------------- scratch (static device memory, no allocs) ----------------
__device__ float g_value[(size_t)T_TOT * DMODEL];
__device__ float g_q    [(size_t)T_TOT * DMODEL];
__device__ float g_off  [(size_t)T_TOT * DMODEL];
__device__ float g_attn [(size_t)T_TOT * (NHEAD * NLEV * NPNT)];
__device__ float g_acc  [(size_t)T_TOT * DMODEL];
__device__ float g_a    [(size_t)T_TOT * DMODEL];
__device__ float g_ff   [(size_t)T_TOT * DFF];
__device__ float g_cur  [(size_t)T_TOT * DMODEL];
__device__ float g_ref  [(size_t)T_TOT * NLEV * 2];

// ---------------- SGEMM: C[M,N] = A[M,K] @ W[K,N] + bias (opt relu) ---------
// BM=BN=128, BK=16, 256 threads, 8x8 microtile per thread.
__global__ __launch_bounds__(256) void sgemm_bias(
    const float* __restrict__ A, const float* __restrict__ W,
    const float* __restrict__ bias, float* __restrict__ C,
    int M, int N, int K, int relu)
{
    __shared__ float As[16][132];   // transposed A tile, padded
    __shared__ float Bs[16][128];

    const int tid  = threadIdx.x;
    const int bm   = blockIdx.y, bn = blockIdx.x;
    const int trow = tid >> 4;      // 0..15
    const int tcol = tid & 15;      // 0..15
    const int rowBase = bm * 128;

    // global-load indexing
    const int aRow0 = tid >> 2;          // 0..63 (+64)
    const int aCol  = (tid & 3) * 4;     // 0,4,8,12
    const int bRow0 = tid >> 5;          // 0..7 (+8)
    const int bCol  = (tid & 31) * 4;    // 0..124

    float acc[8][8];
    #pragma unroll
    for (int i = 0; i < 8; i++)
        #pragma unroll
        for (int j = 0; j < 8; j++) acc[i][j] = 0.f;

    for (int k0 = 0; k0 < K; k0 += 16) {
        #pragma unroll
        for (int i = 0; i < 2; i++) {
            int ar = aRow0 + i * 64;
            int gr = rowBase + ar;
            float4 v = make_float4(0.f, 0.f, 0.f, 0.f);
            if (gr < M) v = *(const float4*)(A + (size_t)gr * K + k0 + aCol);
            As[aCol + 0][ar] = v.x; As[aCol + 1][ar] = v.y;
            As[aCol + 2][ar] = v.z; As[aCol + 3][ar] = v.w;
        }
        #pragma unroll
        for (int i = 0; i < 2; i++) {
            int br = bRow0 + i * 8;
            float4 v = *(const float4*)(W + (size_t)(k0 + br) * N + bn * 128 + bCol);
            *(float4*)(&Bs[br][bCol]) = v;
        }
        __syncthreads();

        #pragma unroll
        for (int kk = 0; kk < 16; kk++) {
            float a[8], b[8];
            *(float4*)(a)     = *(const float4*)(&As[kk][trow * 8]);
            *(float4*)(a + 4) = *(const float4*)(&As[kk][trow * 8 + 4]);
            *(float4*)(b)     = *(const float4*)(&Bs[kk][tcol * 8]);
            *(float4*)(b + 4) = *(const float4*)(&Bs[kk][tcol * 8 + 4]);
            #pragma unroll
            for (int i = 0; i < 8; i++)
                #pragma unroll
                for (int j = 0; j < 8; j++)
                    acc[i][j] = fmaf(a[i], b[j], acc[i][j]);
        }
        __syncthreads();
    }

    float bv[8];
    *(float4*)(bv)     = *(const float4*)(bias + bn * 128 + tcol * 8);
    *(float4*)(bv + 4) = *(const float4*)(bias + bn * 128 + tcol * 8 + 4);

    #pragma unroll
    for (int i = 0; i < 8; i++) {
        int gr = rowBase + trow * 8 + i;
        if (gr < M) {
            float o[8];
            #pragma unroll
            for (int j = 0; j < 8; j++) {
                o[j] = acc[i][j] + bv[j];
                if (relu) o[j] = fmaxf(o[j], 0.f);
            }
            float* cp = C + (size_t)gr * N + bn * 128 + tcol * 8;
            *(float4*)(cp)     = *(float4*)(o);
            *(float4*)(cp + 4) = *(float4*)(o + 4);
        }
    }
}

// ---------------- elementwise add: q = cur + pos ----------------
__global__ void ew_add(const float* __restrict__ x, const float* __restrict__ y,
                       float* __restrict__ out, int n)
{
    int i = blockIdx.x * blockDim.x + threadIdx.x;
    if (i < n) out[i] = x[i] + y[i];
}

// ---------------- reference points ----------------
__global__ void compute_ref(const float* __restrict__ vr, float* __restrict__ ref)
{
    int t = blockIdx.x * blockDim.x + threadIdx.x;
    if (t >= T_TOT) return;
    int b = t / S_TOT;
    int s = t - b * S_TOT;

    int lq, rem;
    if      (s >= 19950) { lq = 3; rem = s - 19950; }
    else if (s >= 19000) { lq = 2; rem = s - 19000; }
    else if (s >= 15200) { lq = 1; rem = s - 15200; }
    else                 { lq = 0; rem = s; }

    int H, W, st;
    level_consts(lq, H, W, st);
    int iy = rem / W;
    int ix = rem - iy * W;

    const float* v = vr + b * (NLEV * 2);
    float rx = (ix + 0.5f) / (v[lq * 2 + 0] * (float)W);
    float ry = (iy + 0.5f) / (v[lq * 2 + 1] * (float)H);

    #pragma unroll
    for (int l = 0; l < 4; l++) {
        ref[(size_t)t * 8 + l * 2 + 0] = rx * v[l * 2 + 0];
        ref[(size_t)t * 8 + l * 2 + 1] = ry * v[l * 2 + 1];
    }
}

// ---------------- softmax over 16 (per token,head) ----------------
__global__ void softmax16(float* __restrict__ attn, int n)
{
    int i = blockIdx.x * blockDim.x + threadIdx.x;
    if (i >= n) return;
    float* p = attn + (size_t)i * 16;
    float v[16], m = -1e30f;
    #pragma unroll
    for (int j = 0; j < 16; j++) { v[j] = p[j]; m = fmaxf(m, v[j]); }
    float s = 0.f;
    #pragma unroll
    for (int j = 0; j < 16; j++) { v[j] = expf(v[j] - m); s += v[j]; }
    float inv = 1.f / s;
    #pragma unroll
    for (int j = 0; j < 16; j++) p[j] = v[j] * inv;
}

// ---------------- MSDA bilinear sampling ----------------
// one block per token (256 thr = 8 warps = 8 heads; lane = head-dim)
__global__ __launch_bounds__(256) void msda_sample(
    const float* __restrict__ value, const float* __restrict__ off,
    const float* __restrict__ attn, const float* __restrict__ ref,
    float* __restrict__ acc)
{
    const int t = blockIdx.x;
    const int h = threadIdx.x >> 5;
    const int d = threadIdx.x & 31;
    const int b = (t >= S_TOT) ? 1 : 0;

    const float* vb = value + (size_t)b * S_TOT * DMODEL;
    const float* rp = ref  + (size_t)t * 8;
    const float* op = off  + (size_t)t * DMODEL + h * 32;  // (h,l,p,2) -> h*32+l*8+p*2
    const float* ap = attn + (size_t)t * 128 + h * 16;
    const int hd = h * HDIM + d;

    float a = 0.f;
    #pragma unroll
    for (int l = 0; l < 4; l++) {
        int Hl, Wl, st;
        level_consts(l, Hl, Wl, st);
        const float* vlev = vb + (size_t)st * DMODEL;
        float rx = rp[l * 2], ry = rp[l * 2 + 1];
        float invW = 1.f / (float)Wl, invH = 1.f / (float)Hl;
        #pragma unroll
        for (int p = 0; p < 4; p++) {
            float ox = op[l * 8 + p * 2], oy = op[l * 8 + p * 2 + 1];
            float w  = ap[l * 4 + p];
            float lx = rx + ox * invW;
            float ly = ry + oy * invH;
            float px = lx * (float)Wl - 0.5f;
            float py = ly * (float)Hl - 0.5f;
            float fx = floorf(px), fy = floorf(py);
            float dx = px - fx, dy = py - fy;
            int x0 = (int)fx, y0 = (int)fy;
            int x1 = x0 + 1, y1 = y0 + 1;
            bool vx0 = (x0 >= 0) & (x0 < Wl), vx1 = (x1 >= 0) & (x1 < Wl);
            bool vy0 = (y0 >= 0) & (y0 < Hl), vy1 = (y1 >= 0) & (y1 < Hl);
            int cx0 = min(max(x0, 0), Wl - 1), cx1 = min(max(x1, 0), Wl - 1);
            int cy0 = min(max(y0, 0), Hl - 1), cy1 = min(max(y1, 0), Hl - 1);
            float w00 = (vx0 && vy0) ? (1.f - dx) * (1.f - dy) : 0.f;
            float w10 = (vx1 && vy0) ? dx * (1.f - dy) : 0.f;
            float w01 = (vx0 && vy1) ? (1.f - dx) * dy : 0.f;
            float w11 = (vx1 && vy1) ? dx * dy : 0.f;
            float v00 = vlev[(size_t)(cy0 * Wl + cx0) * DMODEL + hd];
            float v10 = vlev[(size_t)(cy0 * Wl + cx1) * DMODEL + hd];
            float v01 = vlev[(size_t)(cy1 * Wl + cx0) * DMODEL + hd];
            float v11 = vlev[(size_t)(cy1 * Wl + cx1) * DMODEL + hd];
            float s = v00 * w00 + v10 * w10 + v01 * w01 + v11 * w11;
            a = fmaf(w, s, a);
        }
    }
    acc[(size_t)t * DMODEL + hd] = a;
}

// ---------------- residual add + layernorm (row = 256) ----------------
__global__ __launch_bounds__(256) void add_ln(
    const float* __restrict__ x, const float* __restrict__ r,
    const float* __restrict__ g, const float* __restrict__ bta,
    float* __restrict__ out)
{
    __shared__ float warpsum[8];
    __shared__ float bcast;
    const int row = blockIdx.x, tid = threadIdx.x;
    const int lane = tid & 31, wid = tid >> 5;

    float v = x[(size_t)row * 256 + tid] + r[(size_t)row * 256 + tid];

    float s = v;
    #pragma unroll
    for (int o = 16; o > 0; o >>= 1) s += __shfl_xor_sync(0xFFFFFFFFu, s, o);
    if (lane == 0) warpsum[wid] = s;
    __syncthreads();
    if (tid == 0) {
        float tt = 0.f;
        #pragma unroll
        for (int i = 0; i < 8; i++) tt += warpsum[i];
        bcast = tt * (1.f / 256.f);
    }
    __syncthreads();
    float mean = bcast;
    float dcen = v - mean;

    float s2 = dcen * dcen;
    #pragma unroll
    for (int o = 16; o > 0; o >>= 1) s2 += __shfl_xor_sync(0xFFFFFFFFu, s2, o);
    if (lane == 0) warpsum[wid] = s2;
    __syncthreads();
    if (tid == 0) {
        float tt = 0.f;
        #pragma unroll
        for (int i = 0; i < 8; i++) tt += warpsum[i];
        bcast = tt * (1.f / 256.f);
    }
    __syncthreads();
    float var = bcast;

    out[(size_t)row * 256 + tid] = dcen * rsqrtf(var + 1e-5f) * g[tid] + bta[tid];
}

// ---------------- host orchestration ----------------
static inline void run_gemm(const float* A, const float* W, const float* bias,
                            float* C, int M, int N, int K, int relu)
{
    dim3 grid(N / 128, (M + 127) / 128);
    sgemm_bias<<<grid, 256>>>(A, W, bias, C, M, N, K, relu);
}

extern "C" void kernel_launch(void* const* d_in, const int* in_sizes, int n_in,
                              void* d_out, int out_size)
{
    const float* src     = (const float*)d_in[0];
    const float* pos     = (const float*)d_in[1];
    const float* vratios = (const float*)d_in[2];
    const float* W_value = (const float*)d_in[3];
    const float* b_value = (const float*)d_in[4];
    const float* W_off   = (const float*)d_in[5];
    const float* b_off   = (const float*)d_in[6];
    const float* W_attn  = (const float*)d_in[7];
    const float* b_attn  = (const float*)d_in[8];
    const float* W_out   = (const float*)d_in[9];
    const float* b_out   = (const float*)d_in[10];
    const float* ln1g    = (const float*)d_in[11];
    const float* ln1b    = (const float*)d_in[12];
    const float* W_ff1   = (const float*)d_in[13];
    const float* b_ff1   = (const float*)d_in[14];
    const float* W_ff2   = (const float*)d_in[15];
    const float* b_ff2   = (const float*)d_in[16];
    const float* ln2g    = (const float*)d_in[17];
    const float* ln2b    = (const float*)d_in[18];

    float *pval, *pq, *poff, *pattn, *pacc, *pa, *pff, *pcur, *pref;
    cudaGetSymbolAddress((void**)&pval,  g_value);
    cudaGetSymbolAddress((void**)&pq,    g_q);
    cudaGetSymbolAddress((void**)&poff,  g_off);
    cudaGetSymbolAddress((void**)&pattn, g_attn);
    cudaGetSymbolAddress((void**)&pacc,  g_acc);
    cudaGetSymbolAddress((void**)&pa,    g_a);
    cudaGetSymbolAddress((void**)&pff,   g_ff);
    cudaGetSymbolAddress((void**)&pcur,  g_cur);
    cudaGetSymbolAddress((void**)&pref,  g_ref);

    const int nElem = T_TOT * DMODEL;           // 10,340,864
    const int M = T_TOT;

    // reference points (valid_ratios constant across layers)
    compute_ref<<<(T_TOT + 255) / 256, 256>>>(vratios, pref);

    const float* cur = src;
    for (int i = 0; i < NLAYERS; i++) {
        const float* Wv  = W_value + (size_t)i * DMODEL * DMODEL;
        const float* bv  = b_value + (size_t)i * DMODEL;
        const float* Wof = W_off   + (size_t)i * DMODEL * DMODEL;
        const float* bof = b_off   + (size_t)i * DMODEL;
        const float* Wat = W_attn  + (size_t)i * DMODEL * 128;
        const float* bat = b_attn  + (size_t)i * 128;
        const float* Wo  = W_out   + (size_t)i * DMODEL * DMODEL;
        const float* bo  = b_out   + (size_t)i * DMODEL;
        const float* Wf1 = W_ff1   + (size_t)i * DMODEL * DFF;
        const float* bf1 = b_ff1   + (size_t)i * DFF;
        const float* Wf2 = W_ff2   + (size_t)i * DFF * DMODEL;
        const float* bf2 = b_ff2   + (size_t)i * DMODEL;

        // value projection
        run_gemm(cur, Wv, bv, pval, M, DMODEL, DMODEL, 0);
        // q = cur + pos
        ew_add<<<(nElem + 255) / 256, 256>>>(cur, pos, pq, nElem);
        // offsets / attention logits
        run_gemm(pq, Wof, bof, poff, M, DMODEL, DMODEL, 0);
        run_gemm(pq, Wat, bat, pattn, M, 128, DMODEL, 0);
        softmax16<<<(T_TOT * NHEAD + 255) / 256, 256>>>(pattn, T_TOT * NHEAD);
        // deformable sampling
        msda_sample<<<T_TOT, 256>>>(pval, poff, pattn, pref, pacc);
        // output projection + residual LN
        run_gemm(pacc, Wo, bo, pa, M, DMODEL, DMODEL, 0);
        add_ln<<<T_TOT, 256>>>(cur, pa, ln1g + (size_t)i * DMODEL,
                               ln1b + (size_t)i * DMODEL, pcur);
        // FFN
        run_gemm(pcur, Wf1, bf1, pff, M, DFF, DMODEL, 1);
        run_gemm(pff, Wf2, bf2, pa, M, DMODEL, DFF, 0);
        float* dst = (i == NLAYERS - 1) ? (float*)d_out : pcur;
        add_ln<<<T_TOT, 256>>>(pcur, pa, ln2g + (size_t)i * DMODEL,
                               ln2b + (size_t)i * DMODEL, dst);
        cur = pcur;
    }
}

// round 7
// speedup vs baseline: 1.0026x; 1.0026x over previous
#include <cuda_runtime.h>
#include <math.h>

// ---------------- problem constants ----------------
#define S_TOT   20197
#define BATCH   2
#define T_TOT   40394          // BATCH * S_TOT
#define DMODEL  256
#define NHEAD   8
#define HDIM    32
#define NLEV    4
#define NPNT    4
#define DFF     1024
#define NLAYERS 6

// level geometry
__device__ __forceinline__ void level_consts(int l, int& H, int& W, int& start) {
    const int Hs[4] = {100, 50, 25, 13};
    const int Ws[4] = {152, 76, 38, 19};
    const int St[4] = {0, 15200, 19000, 19950};
    H = Hs[l]; W = Ws[l]; start = St[l];
}

// ---------------- scratch (static device memory, no allocs) ----------------
__device__ float g_value[(size_t)T_TOT * DMODEL];
__device__ float g_q    [(size_t)T_TOT * DMODEL];
__device__ float g_off  [(size_t)T_TOT * DMODEL];
__device__ float g_attn [(size_t)T_TOT * (NHEAD * NLEV * NPNT)];
__device__ float g_acc  [(size_t)T_TOT * DMODEL];
__device__ float g_a    [(size_t)T_TOT * DMODEL];
__device__ float g_ff   [(size_t)T_TOT * DFF];
__device__ float g_cur  [(size_t)T_TOT * DMODEL];
__device__ float g_ref  [(size_t)T_TOT * NLEV * 2];

// ---------------- SGEMM: C[M,N] = A[M,K] @ W[K,N] + bias (opt relu) ---------
// BM=BN=128, BK=16, 256 threads, 8x8 microtile per thread.
__global__ __launch_bounds__(256) void sgemm_bias(
    const float* __restrict__ A, const float* __restrict__ W,
    const float* __restrict__ bias, float* __restrict__ C,
    int M, int N, int K, int relu)
{
    __shared__ float As[16][132];   // transposed A tile, padded
    __shared__ float Bs[16][128];

    const int tid  = threadIdx.x;
    const int bm   = blockIdx.y, bn = blockIdx.x;
    const int trow = tid >> 4;      // 0..15
    const int tcol = tid & 15;      // 0..15
    const int rowBase = bm * 128;

    // global-load indexing
    const int aRow0 = tid >> 2;          // 0..63 (+64)
    const int aCol  = (tid & 3) * 4;     // 0,4,8,12
    const int bRow0 = tid >> 5;          // 0..7 (+8)
    const int bCol  = (tid & 31) * 4;    // 0..124

    float acc[8][8];
    #pragma unroll
    for (int i = 0; i < 8; i++)
        #pragma unroll
        for (int j = 0; j < 8; j++) acc[i][j] = 0.f;

    for (int k0 = 0; k0 < K; k0 += 16) {
        #pragma unroll
        for (int i = 0; i < 2; i++) {
            int ar = aRow0 + i * 64;
            int gr = rowBase + ar;
            float4 v = make_float4(0.f, 0.f, 0.f, 0.f);
            if (gr < M) v = *(const float4*)(A + (size_t)gr * K + k0 + aCol);
            As[aCol + 0][ar] = v.x; As[aCol + 1][ar] = v.y;
            As[aCol + 2][ar] = v.z; As[aCol + 3][ar] = v.w;
        }
        #pragma unroll
        for (int i = 0; i < 2; i++) {
            int br = bRow0 + i * 8;
            float4 v = *(const float4*)(W + (size_t)(k0 + br) * N + bn * 128 + bCol);
            *(float4*)(&Bs[br][bCol]) = v;
        }
        __syncthreads();

        #pragma unroll
        for (int kk = 0; kk < 16; kk++) {
            float a[8], b[8];
            *(float4*)(a)     = *(const float4*)(&As[kk][trow * 8]);
            *(float4*)(a + 4) = *(const float4*)(&As[kk][trow * 8 + 4]);
            *(float4*)(b)     = *(const float4*)(&Bs[kk][tcol * 8]);
            *(float4*)(b + 4) = *(const float4*)(&Bs[kk][tcol * 8 + 4]);
            #pragma unroll
            for (int i = 0; i < 8; i++)
                #pragma unroll
                for (int j = 0; j < 8; j++)
                    acc[i][j] = fmaf(a[i], b[j], acc[i][j]);
        }
        __syncthreads();
    }

    float bv[8];
    *(float4*)(bv)     = *(const float4*)(bias + bn * 128 + tcol * 8);
    *(float4*)(bv + 4) = *(const float4*)(bias + bn * 128 + tcol * 8 + 4);

    #pragma unroll
    for (int i = 0; i < 8; i++) {
        int gr = rowBase + trow * 8 + i;
        if (gr < M) {
            float o[8];
            #pragma unroll
            for (int j = 0; j < 8; j++) {
                o[j] = acc[i][j] + bv[j];
                if (relu) o[j] = fmaxf(o[j], 0.f);
            }
            float* cp = C + (size_t)gr * N + bn * 128 + tcol * 8;
            *(float4*)(cp)     = *(float4*)(o);
            *(float4*)(cp + 4) = *(float4*)(o + 4);
        }
    }
}

// ---------------- elementwise add: q = cur + pos ----------------
__global__ void ew_add(const float* __restrict__ x, const float* __restrict__ y,
                       float* __restrict__ out, int n)
{
    int i = blockIdx.x * blockDim.x + threadIdx.x;
    if (i < n) out[i] = x[i] + y[i];
}

// ---------------- reference points ----------------
__global__ void compute_ref(const float* __restrict__ vr, float* __restrict__ ref)
{
    int t = blockIdx.x * blockDim.x + threadIdx.x;
    if (t >= T_TOT) return;
    int b = t / S_TOT;
    int s = t - b * S_TOT;

    int lq, rem;
    if      (s >= 19950) { lq = 3; rem = s - 19950; }
    else if (s >= 19000) { lq = 2; rem = s - 19000; }
    else if (s >= 15200) { lq = 1; rem = s - 15200; }
    else                 { lq = 0; rem = s; }

    int H, W, st;
    level_consts(lq, H, W, st);
    int iy = rem / W;
    int ix = rem - iy * W;

    const float* v = vr + b * (NLEV * 2);
    float rx = (ix + 0.5f) / (v[lq * 2 + 0] * (float)W);
    float ry = (iy + 0.5f) / (v[lq * 2 + 1] * (float)H);

    #pragma unroll
    for (int l = 0; l < 4; l++) {
        ref[(size_t)t * 8 + l * 2 + 0] = rx * v[l * 2 + 0];
        ref[(size_t)t * 8 + l * 2 + 1] = ry * v[l * 2 + 1];
    }
}

// ---------------- softmax over 16 (per token,head) ----------------
__global__ void softmax16(float* __restrict__ attn, int n)
{
    int i = blockIdx.x * blockDim.x + threadIdx.x;
    if (i >= n) return;
    float* p = attn + (size_t)i * 16;
    float v[16], m = -1e30f;
    #pragma unroll
    for (int j = 0; j < 16; j++) { v[j] = p[j]; m = fmaxf(m, v[j]); }
    float s = 0.f;
    #pragma unroll
    for (int j = 0; j < 16; j++) { v[j] = expf(v[j] - m); s += v[j]; }
    float inv = 1.f / s;
    #pragma unroll
    for (int j = 0; j < 16; j++) p[j] = v[j] * inv;
}

// ---------------- MSDA bilinear sampling ----------------
// one block per token (256 thr = 8 warps = 8 heads; lane = head-dim)
__global__ __launch_bounds__(256) void msda_sample(
    const float* __restrict__ value, const float* __restrict__ off,
    const float* __restrict__ attn, const float* __restrict__ ref,
    float* __restrict__ acc)
{
    const int t = blockIdx.x;
    const int h = threadIdx.x >> 5;
    const int d = threadIdx.x & 31;
    const int b = (t >= S_TOT) ? 1 : 0;

    const float* vb = value + (size_t)b * S_TOT * DMODEL;
    const float* rp = ref  + (size_t)t * 8;
    const float* op = off  + (size_t)t * DMODEL + h * 32;  // (h,l,p,2) -> h*32+l*8+p*2
    const float* ap = attn + (size_t)t * 128 + h * 16;
    const int hd = h * HDIM + d;

    float a = 0.f;
    #pragma unroll
    for (int l = 0; l < 4; l++) {
        int Hl, Wl, st;
        level_consts(l, Hl, Wl, st);
        const float* vlev = vb + (size_t)st * DMODEL;
        float rx = rp[l * 2], ry = rp[l * 2 + 1];
        float invW = 1.f / (float)Wl, invH = 1.f / (float)Hl;
        #pragma unroll
        for (int p = 0; p < 4; p++) {
            float ox = op[l * 8 + p * 2], oy = op[l * 8 + p * 2 + 1];
            float w  = ap[l * 4 + p];
            float lx = rx + ox * invW;
            float ly = ry + oy * invH;
            float px = lx * (float)Wl - 0.5f;
            float py = ly * (float)Hl - 0.5f;
            float fx = floorf(px), fy = floorf(py);
            float dx = px - fx, dy = py - fy;
            int x0 = (int)fx, y0 = (int)fy;
            int x1 = x0 + 1, y1 = y0 + 1;
            bool vx0 = (x0 >= 0) & (x0 < Wl), vx1 = (x1 >= 0) & (x1 < Wl);
            bool vy0 = (y0 >= 0) & (y0 < Hl), vy1 = (y1 >= 0) & (y1 < Hl);
            int cx0 = min(max(x0, 0), Wl - 1), cx1 = min(max(x1, 0), Wl - 1);
            int cy0 = min(max(y0, 0), Hl - 1), cy1 = min(max(y1, 0), Hl - 1);
            float w00 = (vx0 && vy0) ? (1.f - dx) * (1.f - dy) : 0.f;
            float w10 = (vx1 && vy0) ? dx * (1.f - dy) : 0.f;
            float w01 = (vx0 && vy1) ? (1.f - dx) * dy : 0.f;
            float w11 = (vx1 && vy1) ? dx * dy : 0.f;
            float v00 = vlev[(size_t)(cy0 * Wl + cx0) * DMODEL + hd];
            float v10 = vlev[(size_t)(cy0 * Wl + cx1) * DMODEL + hd];
            float v01 = vlev[(size_t)(cy1 * Wl + cx0) * DMODEL + hd];
            float v11 = vlev[(size_t)(cy1 * Wl + cx1) * DMODEL + hd];
            float s = v00 * w00 + v10 * w10 + v01 * w01 + v11 * w11;
            a = fmaf(w, s, a);
        }
    }
    acc[(size_t)t * DMODEL + hd] = a;
}

// ---------------- residual add + layernorm (row = 256) ----------------
__global__ __launch_bounds__(256) void add_ln(
    const float* __restrict__ x, const float* __restrict__ r,
    const float* __restrict__ g, const float* __restrict__ bta,
    float* __restrict__ out)
{
    __shared__ float warpsum[8];
    __shared__ float bcast;
    const int row = blockIdx.x, tid = threadIdx.x;
    const int lane = tid & 31, wid = tid >> 5;

    float v = x[(size_t)row * 256 + tid] + r[(size_t)row * 256 + tid];

    float s = v;
    #pragma unroll
    for (int o = 16; o > 0; o >>= 1) s += __shfl_xor_sync(0xFFFFFFFFu, s, o);
    if (lane == 0) warpsum[wid] = s;
    __syncthreads();
    if (tid == 0) {
        float tt = 0.f;
        #pragma unroll
        for (int i = 0; i < 8; i++) tt += warpsum[i];
        bcast = tt * (1.f / 256.f);
    }
    __syncthreads();
    float mean = bcast;
    float dcen = v - mean;

    float s2 = dcen * dcen;
    #pragma unroll
    for (int o = 16; o > 0; o >>= 1) s2 += __shfl_xor_sync(0xFFFFFFFFu, s2, o);
    if (lane == 0) warpsum[wid] = s2;
    __syncthreads();
    if (tid == 0) {
        float tt = 0.f;
        #pragma unroll
        for (int i = 0; i < 8; i++) tt += warpsum[i];
        bcast = tt * (1.f / 256.f);
    }
    __syncthreads();
    float var = bcast;

    out[(size_t)row * 256 + tid] = dcen * rsqrtf(var + 1e-5f) * g[tid] + bta[tid];
}

// ---------------- host orchestration ----------------
static inline void run_gemm(const float* A, const float* W, const float* bias,
                            float* C, int M, int N, int K, int relu)
{
    dim3 grid(N / 128, (M + 127) / 128);
    sgemm_bias<<<grid, 256>>>(A, W, bias, C, M, N, K, relu);
}

extern "C" void kernel_launch(void* const* d_in, const int* in_sizes, int n_in,
                              void* d_out, int out_size)
{
    const float* src     = (const float*)d_in[0];
    const float* pos     = (const float*)d_in[1];
    const float* vratios = (const float*)d_in[2];
    const float* W_value = (const float*)d_in[3];
    const float* b_value = (const float*)d_in[4];
    const float* W_off   = (const float*)d_in[5];
    const float* b_off   = (const float*)d_in[6];
    const float* W_attn  = (const float*)d_in[7];
    const float* b_attn  = (const float*)d_in[8];
    const float* W_out   = (const float*)d_in[9];
    const float* b_out   = (const float*)d_in[10];
    const float* ln1g    = (const float*)d_in[11];
    const float* ln1b    = (const float*)d_in[12];
    const float* W_ff1   = (const float*)d_in[13];
    const float* b_ff1   = (const float*)d_in[14];
    const float* W_ff2   = (const float*)d_in[15];
    const float* b_ff2   = (const float*)d_in[16];
    const float* ln2g    = (const float*)d_in[17];
    const float* ln2b    = (const float*)d_in[18];

    float *pval, *pq, *poff, *pattn, *pacc, *pa, *pff, *pcur, *pref;
    cudaGetSymbolAddress((void**)&pval,  g_value);
    cudaGetSymbolAddress((void**)&pq,    g_q);
    cudaGetSymbolAddress((void**)&poff,  g_off);
    cudaGetSymbolAddress((void**)&pattn, g_attn);
    cudaGetSymbolAddress((void**)&pacc,  g_acc);
    cudaGetSymbolAddress((void**)&pa,    g_a);
    cudaGetSymbolAddress((void**)&pff,   g_ff);
    cudaGetSymbolAddress((void**)&pcur,  g_cur);
    cudaGetSymbolAddress((void**)&pref,  g_ref);

    const int nElem = T_TOT * DMODEL;           // 10,340,864
    const int M = T_TOT;

    // reference points (valid_ratios constant across layers)
    compute_ref<<<(T_TOT + 255) / 256, 256>>>(vratios, pref);

    const float* cur = src;
    for (int i = 0; i < NLAYERS; i++) {
        const float* Wv  = W_value + (size_t)i * DMODEL * DMODEL;
        const float* bv  = b_value + (size_t)i * DMODEL;
        const float* Wof = W_off   + (size_t)i * DMODEL * DMODEL;
        const float* bof = b_off   + (size_t)i * DMODEL;
        const float* Wat = W_attn  + (size_t)i * DMODEL * 128;
        const float* bat = b_attn  + (size_t)i * 128;
        const float* Wo  = W_out   + (size_t)i * DMODEL * DMODEL;
        const float* bo  = b_out   + (size_t)i * DMODEL;
        const float* Wf1 = W_ff1   + (size_t)i * DMODEL * DFF;
        const float* bf1 = b_ff1   + (size_t)i * DFF;
        const float* Wf2 = W_ff2   + (size_t)i * DFF * DMODEL;
        const float* bf2 = b_ff2   + (size_t)i * DMODEL;

        // value projection
        run_gemm(cur, Wv, bv, pval, M, DMODEL, DMODEL, 0);
        // q = cur + pos
        ew_add<<<(nElem + 255) / 256, 256>>>(cur, pos, pq, nElem);
        // offsets / attention logits
        run_gemm(pq, Wof, bof, poff, M, DMODEL, DMODEL, 0);
        run_gemm(pq, Wat, bat, pattn, M, 128, DMODEL, 0);
        softmax16<<<(T_TOT * NHEAD + 255) / 256, 256>>>(pattn, T_TOT * NHEAD);
        // deformable sampling
        msda_sample<<<T_TOT, 256>>>(pval, poff, pattn, pref, pacc);
        // output projection + residual LN
        run_gemm(pacc, Wo, bo, pa, M, DMODEL, DMODEL, 0);
        add_ln<<<T_TOT, 256>>>(cur, pa, ln1g + (size_t)i * DMODEL,
                               ln1b + (size_t)i * DMODEL, pcur);
        // FFN
        run_gemm(pcur, Wf1, bf1, pff, M, DFF, DMODEL, 1);
        run_gemm(pff, Wf2, bf2, pa, M, DMODEL, DFF, 0);
        float* dst = (i == NLAYERS - 1) ? (float*)d_out : pcur;
        add_ln<<<T_TOT, 256>>>(pcur, pa, ln2g + (size_t)i * DMODEL,
                               ln2b + (size_t)i * DMODEL, dst);
        cur = pcur;
    }
}